// round 9
// baseline (speedup 1.0000x reference)
#include <cuda_runtime.h>
#include <cuda_bf16.h>
#include <math.h>
#include <cstdint>

// ---------------------------------------------------------------------------
// HanningTemplateLayer as band-aligned Toeplitz GEMM on mma.sync (bf16 hi/lo).
// Per 128-col tile: D[m,n] = sum_k T[m,k] * X[n,k],
//   T[m,k] = c[k-m] (zero outside [0,80)),  X[n,k] = x[n, col0-40+k]
//   out[n, col0+m] = D[m,n]
// Warp w owns m in [16w,16w+16); band spans k in [16w,16w+96): 6 k16-steps.
// R9: ldmatrix.x4 B-fragment loads, interleaved hi/lo coeff pair table
//     (LDS.64), vectorized bf16-split prologue, race fix.
// ---------------------------------------------------------------------------

#define THREADS 256
#define TILE_M  128
#define TAPS    80
#define HALF    40
#define L_LEN   65536
#define SROW    264          // uint16 per X row (528B; 132 words, 132%32=4)

// smem byte offsets
#define OFF_CHI   0                     // 128 x u16, band at +24
#define OFF_CLO   256
#define OFF_CPX   512                   // 112 x (u32 hi pair, u32 lo pair)
#define OFF_XHI   1536                  // 64 rows x 528B
#define OFF_XLO   (OFF_XHI + 64*528)
#define SM_TOTAL  (OFF_XLO + 64*528)    // 69120 B

__device__ __forceinline__ void mma_bf16(float* d, uint32_t a0, uint32_t a1,
                                         uint32_t a2, uint32_t a3,
                                         uint32_t b0, uint32_t b1) {
    asm("mma.sync.aligned.m16n8k16.row.col.f32.bf16.bf16.f32 "
        "{%0,%1,%2,%3}, {%4,%5,%6,%7}, {%8,%9}, {%0,%1,%2,%3};"
        : "+f"(d[0]), "+f"(d[1]), "+f"(d[2]), "+f"(d[3])
        : "r"(a0), "r"(a1), "r"(a2), "r"(a3), "r"(b0), "r"(b1));
}

__device__ __forceinline__ void ldsm4(uint32_t& r0, uint32_t& r1,
                                      uint32_t& r2, uint32_t& r3, uint32_t a) {
    asm volatile("ldmatrix.sync.aligned.m8n8.x4.shared.b16 {%0,%1,%2,%3}, [%4];"
                 : "=r"(r0), "=r"(r1), "=r"(r2), "=r"(r3) : "r"(a));
}

// pack two f32 -> bf16x2 {lo: a, hi: b}
__device__ __forceinline__ uint32_t bfpack(float a, float b) {
    uint32_t r;
    asm("cvt.rn.bf16x2.f32 %0, %1, %2;" : "=r"(r) : "f"(b), "f"(a));
    return r;
}

__device__ __forceinline__ uint32_t smem_u32(const void* p) {
    uint32_t a;
    asm("{ .reg .u64 t; cvta.to.shared.u64 t, %1; cvt.u32.u64 %0, t; }"
        : "=r"(a) : "l"(p));
    return a;
}

__device__ __forceinline__ uint16_t bfbits(__nv_bfloat16 h) {
    return *reinterpret_cast<uint16_t*>(&h);
}

__global__ __launch_bounds__(THREADS, 3)
void hann_mma_kernel(const float* __restrict__ x, const float* __restrict__ tw,
                     float* __restrict__ out) {
    extern __shared__ __align__(16) char smem[];
    uint16_t* chi16 = reinterpret_cast<uint16_t*>(smem + OFF_CHI);
    uint16_t* clo16 = reinterpret_cast<uint16_t*>(smem + OFF_CLO);
    uint32_t* cpx   = reinterpret_cast<uint32_t*>(smem + OFF_CPX);
    uint16_t* xhi   = reinterpret_cast<uint16_t*>(smem + OFF_XHI);
    uint16_t* xlo   = reinterpret_cast<uint16_t*>(smem + OFF_XLO);

    const int tid  = threadIdx.x;
    const int col0 = blockIdx.x * TILE_M;

    // -- zero coeff scratch (band written after barrier) ------------------------
    if (tid < 128) { chi16[tid] = 0; clo16[tid] = 0; }

    // -- X tile fill: 64 rows x 26 oct-chunks; fp32 -> bf16 hi/lo ----------------
    #pragma unroll
    for (int it = 0; it < 7; ++it) {
        int idx = tid + it * THREADS;            // < 1664
        if (idx < 1664) {
            int row = idx / 26;
            int c8  = idx - row * 26;
            int kk  = c8 * 8;
            int g   = col0 - HALF + kk;          // 4-aligned
            const float* xr = x + (size_t)row * L_LEN;
            float4 va, vb;
            if (g >= 0 && g + 8 <= L_LEN) {
                va = *reinterpret_cast<const float4*>(xr + g);
                vb = *reinterpret_cast<const float4*>(xr + g + 4);
            } else {
                float tp[8];
                #pragma unroll
                for (int e = 0; e < 8; ++e) {
                    int ge = g + e;
                    tp[e] = (ge >= 0 && ge < L_LEN) ? xr[ge] : 0.0f;
                }
                va = make_float4(tp[0], tp[1], tp[2], tp[3]);
                vb = make_float4(tp[4], tp[5], tp[6], tp[7]);
            }
            uint32_t h01 = bfpack(va.x, va.y), h23 = bfpack(va.z, va.w);
            uint32_t h45 = bfpack(vb.x, vb.y), h67 = bfpack(vb.z, vb.w);
            float l0 = va.x - __uint_as_float(h01 << 16);
            float l1 = va.y - __uint_as_float(h01 & 0xFFFF0000u);
            float l2 = va.z - __uint_as_float(h23 << 16);
            float l3 = va.w - __uint_as_float(h23 & 0xFFFF0000u);
            float l4 = vb.x - __uint_as_float(h45 << 16);
            float l5 = vb.y - __uint_as_float(h45 & 0xFFFF0000u);
            float l6 = vb.z - __uint_as_float(h67 << 16);
            float l7 = vb.w - __uint_as_float(h67 & 0xFFFF0000u);
            uint32_t q01 = bfpack(l0, l1), q23 = bfpack(l2, l3);
            uint32_t q45 = bfpack(l4, l5), q67 = bfpack(l6, l7);
            uint32_t eoff = row * SROW + kk;     // element offset, 8-aligned
            *reinterpret_cast<uint4*>(xhi + eoff) = make_uint4(h01, h23, h45, h67);
            *reinterpret_cast<uint4*>(xlo + eoff) = make_uint4(q01, q23, q45, q67);
        }
    }
    __syncthreads();

    // -- coefficients c[t] (threads 0..79), bf16 hi/lo ---------------------------
    if (tid < TAPS) {
        float w0 = tw[0], w1 = tw[1], w2 = tw[2], w3 = tw[3];
        float mx = fmaxf(fmaxf(w0, w1), fmaxf(w2, w3));
        float e0 = expf(w0 - mx), e1 = expf(w1 - mx);
        float e2 = expf(w2 - mx), e3 = expf(w3 - mx);
        float s  = 1.0f / (e0 + e1 + e2 + e3);
        float p[4] = { e0 * s, e1 * s, e2 * s, e3 * s };
        const int widths[4] = { 10, 20, 30, 40 };
        int dd = tid - HALF;
        float c = 0.0f;
        #pragma unroll
        for (int i = 0; i < 4; ++i) {
            int w = widths[i], k = dd + w;
            if (k >= 0 && k < 2 * w) {
                float h = 0.5f - 0.5f * cosf(6.283185307179586f * (float)k
                                             / (float)(2 * w - 1));
                c = fmaf(p[i], h, c);
            }
        }
        __nv_bfloat16 chh = __float2bfloat16(c);
        __nv_bfloat16 cll = __float2bfloat16(c - __bfloat162float(chh));
        chi16[tid + 24] = bfbits(chh);
        clo16[tid + 24] = bfbits(cll);
    }
    __syncthreads();

    // -- interleaved pair table: cpx[2i]=(c_hi[i+8],c_hi[i+9]), cpx[2i+1]=lo -----
    if (tid < 112) {
        cpx[2 * tid]     = (uint32_t)chi16[tid + 9] << 16 | chi16[tid + 8];
        cpx[2 * tid + 1] = (uint32_t)clo16[tid + 9] << 16 | clo16[tid + 8];
    }
    __syncthreads();

    // -- band-aligned MMA: warp w -> m in [16w,16w+16), k in [16w,16w+96) --------
    const int wid = tid >> 5;
    const int lid = tid & 31;
    const int g   = lid >> 2;
    const int t   = lid & 3;
    const int wm0 = wid * 16;
    const int mg  = col0 + wm0 + g;
    const int lbn  = (lid & 7) + ((lid >> 4) << 3);   // ldmatrix row-in-16
    const int kadd = ((lid >> 3) & 1) << 3;           // +8 k for matrices 1,3
    const uint32_t sb = smem_u32(smem);
    const uint2* cpx2 = reinterpret_cast<const uint2*>(smem + OFF_CPX);

    #pragma unroll
    for (int ch = 0; ch < 2; ++ch) {
        float d[4][4];
        #pragma unroll
        for (int nfi = 0; nfi < 4; ++nfi)
            #pragma unroll
            for (int r = 0; r < 4; ++r) d[nfi][r] = 0.0f;

        // per-lane ldmatrix base addresses (byte)
        uint32_t ah0a = sb + OFF_XHI +
                        ((uint32_t)((ch * 32 + lbn) * SROW + wm0 + kadd) << 1);
        uint32_t ah1a = ah0a + 16 * SROW * 2;
        uint32_t al0a = ah0a + (OFF_XLO - OFF_XHI);
        uint32_t al1a = ah1a + (OFF_XLO - OFF_XHI);

        #pragma unroll
        for (int s = 0; s < 6; ++s) {
            const int base = 16 + 16 * s + 2 * t - g;
            uint2 c0 = cpx2[base];          // (hi, lo) pair at d = k-m
            uint2 cm = cpx2[base - 8];      // row +8
            uint2 cp = cpx2[base + 8];      // k +8

            uint32_t bh0, bh1, bh2, bh3, bl0, bl1, bl2, bl3;
            ldsm4(bh0, bh1, bh2, bh3, ah0a + 32 * s);   // n 0-15 (rel), hi
            ldsm4(bl0, bl1, bl2, bl3, al0a + 32 * s);   // n 0-15, lo
            mma_bf16(d[0], c0.x, cm.x, cp.x, c0.x, bh0, bh1);
            mma_bf16(d[0], c0.x, cm.x, cp.x, c0.x, bl0, bl1);
            mma_bf16(d[0], c0.y, cm.y, cp.y, c0.y, bh0, bh1);
            mma_bf16(d[1], c0.x, cm.x, cp.x, c0.x, bh2, bh3);
            mma_bf16(d[1], c0.x, cm.x, cp.x, c0.x, bl2, bl3);
            mma_bf16(d[1], c0.y, cm.y, cp.y, c0.y, bh2, bh3);

            ldsm4(bh0, bh1, bh2, bh3, ah1a + 32 * s);   // n 16-31, hi
            ldsm4(bl0, bl1, bl2, bl3, al1a + 32 * s);   // n 16-31, lo
            mma_bf16(d[2], c0.x, cm.x, cp.x, c0.x, bh0, bh1);
            mma_bf16(d[2], c0.x, cm.x, cp.x, c0.x, bl0, bl1);
            mma_bf16(d[2], c0.y, cm.y, cp.y, c0.y, bh0, bh1);
            mma_bf16(d[3], c0.x, cm.x, cp.x, c0.x, bh2, bh3);
            mma_bf16(d[3], c0.x, cm.x, cp.x, c0.x, bl2, bl3);
            mma_bf16(d[3], c0.y, cm.y, cp.y, c0.y, bh2, bh3);
        }

        // epilogue for this chunk: D[m,n] -> out[n, col0 + m]
        #pragma unroll
        for (int nfi = 0; nfi < 4; ++nfi) {
            const size_t n0 = (size_t)((ch * 4 + nfi) * 8 + 2 * t) * L_LEN;
            out[n0 + mg]             = d[nfi][0];
            out[n0 + L_LEN + mg]     = d[nfi][1];
            out[n0 + mg + 8]         = d[nfi][2];
            out[n0 + L_LEN + mg + 8] = d[nfi][3];
        }
    }
}

extern "C" void kernel_launch(void* const* d_in, const int* in_sizes, int n_in,
                              void* d_out, int out_size) {
    const float* x  = (const float*)d_in[0];   // [64, 65536] fp32
    const float* tw = (const float*)d_in[1];   // [4] fp32
    float* out = (float*)d_out;

    cudaFuncSetAttribute(hann_mma_kernel,
                         cudaFuncAttributeMaxDynamicSharedMemorySize, SM_TOTAL);
    hann_mma_kernel<<<L_LEN / TILE_M, THREADS, SM_TOTAL>>>(x, tw, out);
}

// round 10
// speedup vs baseline: 1.0555x; 1.0555x over previous
#include <cuda_runtime.h>
#include <cuda_bf16.h>
#include <math.h>
#include <cstdint>

// ---------------------------------------------------------------------------
// HanningTemplateLayer as band-aligned Toeplitz GEMM on mma.sync (bf16 hi/lo).
// Per 128-col tile: D[m,n] = sum_k T[m,k] * X[n,k],
//   T[m,k] = c[k-m] (zero outside [0,80)),  X[n,k] = x[n, col0-40+k]
//   out[n, col0+m] = D[m,n]
// Warp w owns m in [16w,16w+16); its band spans k in [16w,16w+96): 6 k-steps.
// R10 = R8 structure (scalar B loads, 2 nf-chunks, 3 CTAs/SM) with the MMA
// stream reordered product-major so same-accumulator HMMAs are 4 apart, and
// all 16 B loads of a k-step issued before any MMA.  Race fix kept from R9.
// ---------------------------------------------------------------------------

#define THREADS 256
#define TILE_M  128
#define TAPS    80
#define HALF    40
#define L_LEN   65536
#define SROW    264          // uint16 per X row (528B; stride mod 128 = 16)
#define SROW2   132          // uint32 stride per X row

// smem byte offsets
#define OFF_CHI   0                     // 128 x u16 bf16(c_hi), band at +24
#define OFF_CLO   256
#define OFF_CPH   512                   // 112 x u32 pair table
#define OFF_CPL   1024
#define OFF_XHI   1536                  // 64 rows x 528B
#define OFF_XLO   (1536 + 64*528)
#define SM_TOTAL  (1536 + 2*64*528)     // 69120 B

__device__ __forceinline__ void mma_bf16(float* d, uint32_t a0, uint32_t a1,
                                         uint32_t a2, uint32_t a3,
                                         uint32_t b0, uint32_t b1) {
    asm("mma.sync.aligned.m16n8k16.row.col.f32.bf16.bf16.f32 "
        "{%0,%1,%2,%3}, {%4,%5,%6,%7}, {%8,%9}, {%0,%1,%2,%3};"
        : "+f"(d[0]), "+f"(d[1]), "+f"(d[2]), "+f"(d[3])
        : "r"(a0), "r"(a1), "r"(a2), "r"(a3), "r"(b0), "r"(b1));
}

__device__ __forceinline__ uint16_t bfbits(__nv_bfloat16 h) {
    return *reinterpret_cast<uint16_t*>(&h);
}

__global__ __launch_bounds__(THREADS, 3)
void hann_mma_kernel(const float* __restrict__ x, const float* __restrict__ tw,
                     float* __restrict__ out) {
    extern __shared__ __align__(16) char smem[];
    uint16_t* chi16 = reinterpret_cast<uint16_t*>(smem + OFF_CHI);
    uint16_t* clo16 = reinterpret_cast<uint16_t*>(smem + OFF_CLO);
    uint32_t* cph   = reinterpret_cast<uint32_t*>(smem + OFF_CPH);
    uint32_t* cpl   = reinterpret_cast<uint32_t*>(smem + OFF_CPL);
    uint16_t* xhi   = reinterpret_cast<uint16_t*>(smem + OFF_XHI);
    uint16_t* xlo   = reinterpret_cast<uint16_t*>(smem + OFF_XLO);

    const int tid  = threadIdx.x;
    const int col0 = blockIdx.x * TILE_M;

    // -- zero coeff scratch (band written after the barrier below) -------------
    if (tid < 128) { chi16[tid] = 0; clo16[tid] = 0; }

    // -- X tile fill: 64 rows x 52 quads; fp32 -> bf16 hi/lo -------------------
    #pragma unroll
    for (int it = 0; it < 13; ++it) {
        int idx = tid + it * THREADS;            // < 3328
        int row = idx / 52;
        int q   = idx - row * 52;
        int kk  = q * 4;
        int g   = col0 - HALF + kk;              // 4-aligned
        float4 v = make_float4(0.f, 0.f, 0.f, 0.f);
        if (g >= 0 && g + 3 < L_LEN)
            v = *reinterpret_cast<const float4*>(x + (size_t)row * L_LEN + g);
        __nv_bfloat16 h0 = __float2bfloat16(v.x), h1 = __float2bfloat16(v.y);
        __nv_bfloat16 h2 = __float2bfloat16(v.z), h3 = __float2bfloat16(v.w);
        __nv_bfloat16 l0 = __float2bfloat16(v.x - __bfloat162float(h0));
        __nv_bfloat16 l1 = __float2bfloat16(v.y - __bfloat162float(h1));
        __nv_bfloat16 l2 = __float2bfloat16(v.z - __bfloat162float(h2));
        __nv_bfloat16 l3 = __float2bfloat16(v.w - __bfloat162float(h3));
        uint32_t eoff = row * SROW + kk;         // element offset, 4-aligned
        *reinterpret_cast<uint2*>(xhi + eoff) = make_uint2(
            (uint32_t)bfbits(h1) << 16 | bfbits(h0),
            (uint32_t)bfbits(h3) << 16 | bfbits(h2));
        *reinterpret_cast<uint2*>(xlo + eoff) = make_uint2(
            (uint32_t)bfbits(l1) << 16 | bfbits(l0),
            (uint32_t)bfbits(l3) << 16 | bfbits(l2));
    }
    __syncthreads();   // orders coeff-scratch zeroing before the band write

    // -- coefficients c[t] (threads 0..79), bf16 hi/lo -------------------------
    if (tid < TAPS) {
        float w0 = tw[0], w1 = tw[1], w2 = tw[2], w3 = tw[3];
        float mx = fmaxf(fmaxf(w0, w1), fmaxf(w2, w3));
        float e0 = expf(w0 - mx), e1 = expf(w1 - mx);
        float e2 = expf(w2 - mx), e3 = expf(w3 - mx);
        float s  = 1.0f / (e0 + e1 + e2 + e3);
        float p[4] = { e0 * s, e1 * s, e2 * s, e3 * s };
        const int widths[4] = { 10, 20, 30, 40 };
        int dd = tid - HALF;
        float c = 0.0f;
        #pragma unroll
        for (int i = 0; i < 4; ++i) {
            int w = widths[i], k = dd + w;
            if (k >= 0 && k < 2 * w) {
                float h = 0.5f - 0.5f * cosf(6.283185307179586f * (float)k
                                             / (float)(2 * w - 1));
                c = fmaf(p[i], h, c);
            }
        }
        __nv_bfloat16 chh = __float2bfloat16(c);
        __nv_bfloat16 cll = __float2bfloat16(c - __bfloat162float(chh));
        chi16[tid + 24] = bfbits(chh);
        clo16[tid + 24] = bfbits(cll);
    }
    __syncthreads();

    // -- pair tables: cpair[16 + d] = (c[d], c[d+1]), d in [-16, 96) -----------
    if (tid < 112) {
        cph[tid] = (uint32_t)chi16[tid + 9] << 16 | chi16[tid + 8];
        cpl[tid] = (uint32_t)clo16[tid + 9] << 16 | clo16[tid + 8];
    }
    __syncthreads();

    // -- band-aligned MMA: warp w -> m in [16w,16w+16), k in [16w,16w+96) ------
    const int wid = tid >> 5;
    const int lid = tid & 31;
    const int g   = lid >> 2;                 // group (row / n within frag)
    const int t   = lid & 3;                  // thread-in-group
    const int wm0 = wid * 16;
    const int mg  = col0 + wm0 + g;

    #pragma unroll
    for (int ch = 0; ch < 2; ++ch) {
        float d[4][4];
        #pragma unroll
        for (int nfi = 0; nfi < 4; ++nfi)
            #pragma unroll
            for (int r = 0; r < 4; ++r) d[nfi][r] = 0.0f;

        #pragma unroll
        for (int s = 0; s < 6; ++s) {
            // A fragments: ah3 == ah0, al3 == al0 (Toeplitz row shift)
            const int base = 16 + 16 * s + 2 * t - g;
            uint32_t ah0 = cph[base];
            uint32_t ah1 = cph[base - 8];
            uint32_t ah2 = cph[base + 8];
            uint32_t al0 = cpl[base];
            uint32_t al1 = cpl[base - 8];
            uint32_t al2 = cpl[base + 8];

            const int ki = ((wm0 + 16 * s) >> 1) + t;   // uint32 index of k+2t

            // load ALL B fragments for this k-step first
            uint32_t bh0[4], bh1[4], bl0[4], bl1[4];
            #pragma unroll
            for (int nfi = 0; nfi < 4; ++nfi) {
                const int n = (ch * 4 + nfi) * 8 + g;
                const uint32_t* ph = reinterpret_cast<const uint32_t*>(xhi) + n * SROW2;
                const uint32_t* pl = reinterpret_cast<const uint32_t*>(xlo) + n * SROW2;
                bh0[nfi] = ph[ki]; bh1[nfi] = ph[ki + 4];
                bl0[nfi] = pl[ki]; bl1[nfi] = pl[ki + 4];
            }

            // product-major MMA stream: same-acc dependency distance = 4
            #pragma unroll
            for (int nfi = 0; nfi < 4; ++nfi)
                mma_bf16(d[nfi], ah0, ah1, ah2, ah0, bh0[nfi], bh1[nfi]);
            #pragma unroll
            for (int nfi = 0; nfi < 4; ++nfi)
                mma_bf16(d[nfi], ah0, ah1, ah2, ah0, bl0[nfi], bl1[nfi]);
            #pragma unroll
            for (int nfi = 0; nfi < 4; ++nfi)
                mma_bf16(d[nfi], al0, al1, al2, al0, bh0[nfi], bh1[nfi]);
        }

        // epilogue for this chunk: D[m,n] -> out[n, col0 + m]
        #pragma unroll
        for (int nfi = 0; nfi < 4; ++nfi) {
            const size_t n0 = (size_t)((ch * 4 + nfi) * 8 + 2 * t) * L_LEN;
            out[n0 + mg]             = d[nfi][0];
            out[n0 + L_LEN + mg]     = d[nfi][1];
            out[n0 + mg + 8]         = d[nfi][2];
            out[n0 + L_LEN + mg + 8] = d[nfi][3];
        }
    }
}

extern "C" void kernel_launch(void* const* d_in, const int* in_sizes, int n_in,
                              void* d_out, int out_size) {
    const float* x  = (const float*)d_in[0];   // [64, 65536] fp32
    const float* tw = (const float*)d_in[1];   // [4] fp32
    float* out = (float*)d_out;

    cudaFuncSetAttribute(hann_mma_kernel,
                         cudaFuncAttributeMaxDynamicSharedMemorySize, SM_TOTAL);
    hann_mma_kernel<<<L_LEN / TILE_M, THREADS, SM_TOTAL>>>(x, tw, out);
}

// round 11
// speedup vs baseline: 1.1404x; 1.0805x over previous
#include <cuda_runtime.h>
#include <cuda_bf16.h>
#include <math.h>
#include <cstdint>

// ---------------------------------------------------------------------------
// HanningTemplateLayer as band-aligned Toeplitz GEMM on mma.sync (bf16 hi/lo).
// CTA = 128 output columns x 32 batch rows.  grid = (512 tiles, 2 row-halves).
//   D[m,n] = sum_k T[m,k] * X[n,k];  T[m,k] = c[k-m];  X[n,k] = x[rb+n, col0-40+k]
//   out[rb+n, col0+m] = D[m,n]
// Warp w owns m in [16w,16w+16); band spans k in [16w,16w+96): 6 k16-steps.
// 3 products: Ah*Bh + Ah*Bl + Al*Bh (fp32 accumulate), rel_err ~4e-6.
// R11: 32 rows/CTA (half the R8 CTA) -> smaller tail quantum, 4 CTAs/SM.
// ---------------------------------------------------------------------------

#define THREADS 256
#define TILE_M  128
#define ROWS    32
#define TAPS    80
#define HALF    40
#define L_LEN   65536
#define SROW    264          // uint16 per X row (528B; stride mod 128 = 16)
#define SROW2   132          // uint32 stride per X row

// smem byte offsets
#define OFF_CHI   0                     // 128 x u16 bf16(c_hi), band at +24
#define OFF_CLO   256
#define OFF_CPH   512                   // 112 x u32 pair table
#define OFF_CPL   1024
#define OFF_XHI   1536                  // 32 rows x 528B
#define OFF_XLO   (OFF_XHI + ROWS*528)
#define SM_TOTAL  (OFF_XLO + ROWS*528)  // 35328 B

__device__ __forceinline__ void mma_bf16(float* d, uint32_t a0, uint32_t a1,
                                         uint32_t a2, uint32_t a3,
                                         uint32_t b0, uint32_t b1) {
    asm("mma.sync.aligned.m16n8k16.row.col.f32.bf16.bf16.f32 "
        "{%0,%1,%2,%3}, {%4,%5,%6,%7}, {%8,%9}, {%0,%1,%2,%3};"
        : "+f"(d[0]), "+f"(d[1]), "+f"(d[2]), "+f"(d[3])
        : "r"(a0), "r"(a1), "r"(a2), "r"(a3), "r"(b0), "r"(b1));
}

__device__ __forceinline__ uint16_t bfbits(__nv_bfloat16 h) {
    return *reinterpret_cast<uint16_t*>(&h);
}

__global__ __launch_bounds__(THREADS, 4)
void hann_mma_kernel(const float* __restrict__ x, const float* __restrict__ tw,
                     float* __restrict__ out) {
    extern __shared__ __align__(16) char smem[];
    uint16_t* chi16 = reinterpret_cast<uint16_t*>(smem + OFF_CHI);
    uint16_t* clo16 = reinterpret_cast<uint16_t*>(smem + OFF_CLO);
    uint32_t* cph   = reinterpret_cast<uint32_t*>(smem + OFF_CPH);
    uint32_t* cpl   = reinterpret_cast<uint32_t*>(smem + OFF_CPL);
    uint16_t* xhi   = reinterpret_cast<uint16_t*>(smem + OFF_XHI);
    uint16_t* xlo   = reinterpret_cast<uint16_t*>(smem + OFF_XLO);

    const int tid  = threadIdx.x;
    const int col0 = blockIdx.x * TILE_M;
    const int rb   = blockIdx.y * ROWS;       // batch-row base of this CTA

    // -- zero coeff scratch (band written after the barrier below) -------------
    if (tid < 128) { chi16[tid] = 0; clo16[tid] = 0; }

    // -- X tile fill: 32 rows x 52 quads; fp32 -> bf16 hi/lo -------------------
    #pragma unroll
    for (int it = 0; it < 7; ++it) {
        int idx = tid + it * THREADS;            // < 1664
        if (idx < ROWS * 52) {
            int row = idx / 52;
            int q   = idx - row * 52;
            int kk  = q * 4;
            int g   = col0 - HALF + kk;          // 4-aligned
            float4 v = make_float4(0.f, 0.f, 0.f, 0.f);
            if (g >= 0 && g + 3 < L_LEN)
                v = *reinterpret_cast<const float4*>(x + (size_t)(rb + row) * L_LEN + g);
            __nv_bfloat16 h0 = __float2bfloat16(v.x), h1 = __float2bfloat16(v.y);
            __nv_bfloat16 h2 = __float2bfloat16(v.z), h3 = __float2bfloat16(v.w);
            __nv_bfloat16 l0 = __float2bfloat16(v.x - __bfloat162float(h0));
            __nv_bfloat16 l1 = __float2bfloat16(v.y - __bfloat162float(h1));
            __nv_bfloat16 l2 = __float2bfloat16(v.z - __bfloat162float(h2));
            __nv_bfloat16 l3 = __float2bfloat16(v.w - __bfloat162float(h3));
            uint32_t eoff = row * SROW + kk;     // element offset, 4-aligned
            *reinterpret_cast<uint2*>(xhi + eoff) = make_uint2(
                (uint32_t)bfbits(h1) << 16 | bfbits(h0),
                (uint32_t)bfbits(h3) << 16 | bfbits(h2));
            *reinterpret_cast<uint2*>(xlo + eoff) = make_uint2(
                (uint32_t)bfbits(l1) << 16 | bfbits(l0),
                (uint32_t)bfbits(l3) << 16 | bfbits(l2));
        }
    }
    __syncthreads();   // orders coeff-scratch zeroing before the band write

    // -- coefficients c[t] (threads 0..79), bf16 hi/lo -------------------------
    if (tid < TAPS) {
        float w0 = tw[0], w1 = tw[1], w2 = tw[2], w3 = tw[3];
        float mx = fmaxf(fmaxf(w0, w1), fmaxf(w2, w3));
        float e0 = expf(w0 - mx), e1 = expf(w1 - mx);
        float e2 = expf(w2 - mx), e3 = expf(w3 - mx);
        float s  = 1.0f / (e0 + e1 + e2 + e3);
        float p[4] = { e0 * s, e1 * s, e2 * s, e3 * s };
        const int widths[4] = { 10, 20, 30, 40 };
        int dd = tid - HALF;
        float c = 0.0f;
        #pragma unroll
        for (int i = 0; i < 4; ++i) {
            int w = widths[i], k = dd + w;
            if (k >= 0 && k < 2 * w) {
                float h = 0.5f - 0.5f * cosf(6.283185307179586f * (float)k
                                             / (float)(2 * w - 1));
                c = fmaf(p[i], h, c);
            }
        }
        __nv_bfloat16 chh = __float2bfloat16(c);
        __nv_bfloat16 cll = __float2bfloat16(c - __bfloat162float(chh));
        chi16[tid + 24] = bfbits(chh);
        clo16[tid + 24] = bfbits(cll);
    }
    __syncthreads();

    // -- pair tables: cpair[16 + d] = (c[d], c[d+1]), d in [-16, 96) -----------
    if (tid < 112) {
        cph[tid] = (uint32_t)chi16[tid + 9] << 16 | chi16[tid + 8];
        cpl[tid] = (uint32_t)clo16[tid + 9] << 16 | clo16[tid + 8];
    }
    __syncthreads();

    // -- band-aligned MMA: warp w -> m in [16w,16w+16), k in [16w,16w+96) ------
    const int wid = tid >> 5;
    const int lid = tid & 31;
    const int g   = lid >> 2;                 // group (row / n within frag)
    const int t   = lid & 3;                  // thread-in-group
    const int wm0 = wid * 16;
    const int mg  = col0 + wm0 + g;

    float d[4][4];
    #pragma unroll
    for (int nfi = 0; nfi < 4; ++nfi)
        #pragma unroll
        for (int r = 0; r < 4; ++r) d[nfi][r] = 0.0f;

    #pragma unroll
    for (int s = 0; s < 6; ++s) {
        // A fragments: ah3 == ah0, al3 == al0 (Toeplitz row shift)
        const int base = 16 + 16 * s + 2 * t - g;
        uint32_t ah0 = cph[base];
        uint32_t ah1 = cph[base - 8];
        uint32_t ah2 = cph[base + 8];
        uint32_t al0 = cpl[base];
        uint32_t al1 = cpl[base - 8];
        uint32_t al2 = cpl[base + 8];

        const int ki = ((wm0 + 16 * s) >> 1) + t;   // uint32 index of k+2t

        // load ALL B fragments for this k-step first
        uint32_t bh0[4], bh1[4], bl0[4], bl1[4];
        #pragma unroll
        for (int nfi = 0; nfi < 4; ++nfi) {
            const int n = nfi * 8 + g;
            const uint32_t* ph = reinterpret_cast<const uint32_t*>(xhi) + n * SROW2;
            const uint32_t* pl = reinterpret_cast<const uint32_t*>(xlo) + n * SROW2;
            bh0[nfi] = ph[ki]; bh1[nfi] = ph[ki + 4];
            bl0[nfi] = pl[ki]; bl1[nfi] = pl[ki + 4];
        }

        // product-major MMA stream: same-acc dependency distance = 4
        #pragma unroll
        for (int nfi = 0; nfi < 4; ++nfi)
            mma_bf16(d[nfi], ah0, ah1, ah2, ah0, bh0[nfi], bh1[nfi]);
        #pragma unroll
        for (int nfi = 0; nfi < 4; ++nfi)
            mma_bf16(d[nfi], ah0, ah1, ah2, ah0, bl0[nfi], bl1[nfi]);
        #pragma unroll
        for (int nfi = 0; nfi < 4; ++nfi)
            mma_bf16(d[nfi], al0, al1, al2, al0, bh0[nfi], bh1[nfi]);
    }

    // -- epilogue: D[m,n] -> out[rb + n, col0 + m] ------------------------------
    #pragma unroll
    for (int nfi = 0; nfi < 4; ++nfi) {
        const size_t n0 = (size_t)(rb + nfi * 8 + 2 * t) * L_LEN;
        out[n0 + mg]             = d[nfi][0];
        out[n0 + L_LEN + mg]     = d[nfi][1];
        out[n0 + mg + 8]         = d[nfi][2];
        out[n0 + L_LEN + mg + 8] = d[nfi][3];
    }
}

extern "C" void kernel_launch(void* const* d_in, const int* in_sizes, int n_in,
                              void* d_out, int out_size) {
    const float* x  = (const float*)d_in[0];   // [64, 65536] fp32
    const float* tw = (const float*)d_in[1];   // [4] fp32
    float* out = (float*)d_out;

    cudaFuncSetAttribute(hann_mma_kernel,
                         cudaFuncAttributeMaxDynamicSharedMemorySize, SM_TOTAL);
    dim3 grid(L_LEN / TILE_M, 64 / ROWS);      // (512, 2) = 1024 CTAs
    hann_mma_kernel<<<grid, THREADS, SM_TOTAL>>>(x, tw, out);
}

// round 12
// speedup vs baseline: 1.1556x; 1.0133x over previous
#include <cuda_runtime.h>
#include <cuda_bf16.h>
#include <math.h>
#include <cstdint>

// ---------------------------------------------------------------------------
// HanningTemplateLayer as band-aligned Toeplitz GEMM on mma.sync (bf16 hi/lo).
// CTA = 128 output columns x 32 batch rows.  grid = (512 tiles, 2 row-halves).
//   D[m,n] = sum_k T[m,k] * X[n,k];  T[m,k] = c[k-m];  X[n,k] = x[rb+n, col0-40+k]
//   out[rb+n, col0+m] = D[m,n]
// Warp w owns m in [16w,16w+16); band spans k in [16w,16w+96): 6 k16-steps.
// 3 products: Ah*Bh + Ah*Bl + Al*Bh (fp32 accumulate), rel_err ~4e-6.
// R12 = R11 mainloop + vectorized bf16x2 prologue (cvt.rn.bf16x2.f32).
// ---------------------------------------------------------------------------

#define THREADS 256
#define TILE_M  128
#define ROWS    32
#define TAPS    80
#define HALF    40
#define L_LEN   65536
#define SROW    264          // uint16 per X row (528B; stride mod 128 = 16)
#define SROW2   132          // uint32 stride per X row

// smem byte offsets
#define OFF_CHI   0                     // 128 x u16 bf16(c_hi), band at +24
#define OFF_CLO   256
#define OFF_CPH   512                   // 112 x u32 pair table
#define OFF_CPL   1024
#define OFF_XHI   1536                  // 32 rows x 528B
#define OFF_XLO   (OFF_XHI + ROWS*528)
#define SM_TOTAL  (OFF_XLO + ROWS*528)  // 35328 B

__device__ __forceinline__ void mma_bf16(float* d, uint32_t a0, uint32_t a1,
                                         uint32_t a2, uint32_t a3,
                                         uint32_t b0, uint32_t b1) {
    asm("mma.sync.aligned.m16n8k16.row.col.f32.bf16.bf16.f32 "
        "{%0,%1,%2,%3}, {%4,%5,%6,%7}, {%8,%9}, {%0,%1,%2,%3};"
        : "+f"(d[0]), "+f"(d[1]), "+f"(d[2]), "+f"(d[3])
        : "r"(a0), "r"(a1), "r"(a2), "r"(a3), "r"(b0), "r"(b1));
}

// pack two f32 -> bf16x2 {lo half: a, hi half: b}
__device__ __forceinline__ uint32_t bfpack(float a, float b) {
    uint32_t r;
    asm("cvt.rn.bf16x2.f32 %0, %1, %2;" : "=r"(r) : "f"(b), "f"(a));
    return r;
}

__device__ __forceinline__ uint16_t bfbits(__nv_bfloat16 h) {
    return *reinterpret_cast<uint16_t*>(&h);
}

__global__ __launch_bounds__(THREADS, 4)
void hann_mma_kernel(const float* __restrict__ x, const float* __restrict__ tw,
                     float* __restrict__ out) {
    extern __shared__ __align__(16) char smem[];
    uint16_t* chi16 = reinterpret_cast<uint16_t*>(smem + OFF_CHI);
    uint16_t* clo16 = reinterpret_cast<uint16_t*>(smem + OFF_CLO);
    uint32_t* cph   = reinterpret_cast<uint32_t*>(smem + OFF_CPH);
    uint32_t* cpl   = reinterpret_cast<uint32_t*>(smem + OFF_CPL);
    uint16_t* xhi   = reinterpret_cast<uint16_t*>(smem + OFF_XHI);
    uint16_t* xlo   = reinterpret_cast<uint16_t*>(smem + OFF_XLO);

    const int tid  = threadIdx.x;
    const int col0 = blockIdx.x * TILE_M;
    const int rb   = blockIdx.y * ROWS;       // batch-row base of this CTA

    // -- zero coeff scratch (band written after the barrier below) -------------
    if (tid < 128) { chi16[tid] = 0; clo16[tid] = 0; }

    // -- X tile fill: 32 rows x 26 oct-chunks; fp32 -> bf16 hi/lo (vectorized) --
    #pragma unroll
    for (int it = 0; it < 4; ++it) {
        int idx = tid + it * THREADS;            // < 1024
        if (idx < ROWS * 26) {
            int row = idx / 26;
            int c8  = idx - row * 26;
            int kk  = c8 * 8;
            int g   = col0 - HALF + kk;          // 4-aligned
            const float* xr = x + (size_t)(rb + row) * L_LEN;
            float4 va, vb;
            if (g >= 0 && g + 8 <= L_LEN) {
                va = *reinterpret_cast<const float4*>(xr + g);
                vb = *reinterpret_cast<const float4*>(xr + g + 4);
            } else {
                float tp[8];
                #pragma unroll
                for (int e = 0; e < 8; ++e) {
                    int ge = g + e;
                    tp[e] = (ge >= 0 && ge < L_LEN) ? xr[ge] : 0.0f;
                }
                va = make_float4(tp[0], tp[1], tp[2], tp[3]);
                vb = make_float4(tp[4], tp[5], tp[6], tp[7]);
            }
            uint32_t h01 = bfpack(va.x, va.y), h23 = bfpack(va.z, va.w);
            uint32_t h45 = bfpack(vb.x, vb.y), h67 = bfpack(vb.z, vb.w);
            float l0 = va.x - __uint_as_float(h01 << 16);
            float l1 = va.y - __uint_as_float(h01 & 0xFFFF0000u);
            float l2 = va.z - __uint_as_float(h23 << 16);
            float l3 = va.w - __uint_as_float(h23 & 0xFFFF0000u);
            float l4 = vb.x - __uint_as_float(h45 << 16);
            float l5 = vb.y - __uint_as_float(h45 & 0xFFFF0000u);
            float l6 = vb.z - __uint_as_float(h67 << 16);
            float l7 = vb.w - __uint_as_float(h67 & 0xFFFF0000u);
            uint32_t q01 = bfpack(l0, l1), q23 = bfpack(l2, l3);
            uint32_t q45 = bfpack(l4, l5), q67 = bfpack(l6, l7);
            uint32_t eoff = row * SROW + kk;     // element offset, 8-aligned
            *reinterpret_cast<uint4*>(xhi + eoff) = make_uint4(h01, h23, h45, h67);
            *reinterpret_cast<uint4*>(xlo + eoff) = make_uint4(q01, q23, q45, q67);
        }
    }
    __syncthreads();   // orders coeff-scratch zeroing before the band write

    // -- coefficients c[t] (threads 0..79), bf16 hi/lo -------------------------
    if (tid < TAPS) {
        float w0 = tw[0], w1 = tw[1], w2 = tw[2], w3 = tw[3];
        float mx = fmaxf(fmaxf(w0, w1), fmaxf(w2, w3));
        float e0 = expf(w0 - mx), e1 = expf(w1 - mx);
        float e2 = expf(w2 - mx), e3 = expf(w3 - mx);
        float s  = 1.0f / (e0 + e1 + e2 + e3);
        float p[4] = { e0 * s, e1 * s, e2 * s, e3 * s };
        const int widths[4] = { 10, 20, 30, 40 };
        int dd = tid - HALF;
        float c = 0.0f;
        #pragma unroll
        for (int i = 0; i < 4; ++i) {
            int w = widths[i], k = dd + w;
            if (k >= 0 && k < 2 * w) {
                float h = 0.5f - 0.5f * cosf(6.283185307179586f * (float)k
                                             / (float)(2 * w - 1));
                c = fmaf(p[i], h, c);
            }
        }
        __nv_bfloat16 chh = __float2bfloat16(c);
        __nv_bfloat16 cll = __float2bfloat16(c - __bfloat162float(chh));
        chi16[tid + 24] = bfbits(chh);
        clo16[tid + 24] = bfbits(cll);
    }
    __syncthreads();

    // -- pair tables: cpair[16 + d] = (c[d], c[d+1]), d in [-16, 96) -----------
    if (tid < 112) {
        cph[tid] = (uint32_t)chi16[tid + 9] << 16 | chi16[tid + 8];
        cpl[tid] = (uint32_t)clo16[tid + 9] << 16 | clo16[tid + 8];
    }
    __syncthreads();

    // -- band-aligned MMA: warp w -> m in [16w,16w+16), k in [16w,16w+96) ------
    const int wid = tid >> 5;
    const int lid = tid & 31;
    const int g   = lid >> 2;                 // group (row / n within frag)
    const int t   = lid & 3;                  // thread-in-group
    const int wm0 = wid * 16;
    const int mg  = col0 + wm0 + g;

    float d[4][4];
    #pragma unroll
    for (int nfi = 0; nfi < 4; ++nfi)
        #pragma unroll
        for (int r = 0; r < 4; ++r) d[nfi][r] = 0.0f;

    #pragma unroll
    for (int s = 0; s < 6; ++s) {
        // A fragments: ah3 == ah0, al3 == al0 (Toeplitz row shift)
        const int base = 16 + 16 * s + 2 * t - g;
        uint32_t ah0 = cph[base];
        uint32_t ah1 = cph[base - 8];
        uint32_t ah2 = cph[base + 8];
        uint32_t al0 = cpl[base];
        uint32_t al1 = cpl[base - 8];
        uint32_t al2 = cpl[base + 8];

        const int ki = ((wm0 + 16 * s) >> 1) + t;   // uint32 index of k+2t

        // load ALL B fragments for this k-step first
        uint32_t bh0[4], bh1[4], bl0[4], bl1[4];
        #pragma unroll
        for (int nfi = 0; nfi < 4; ++nfi) {
            const int n = nfi * 8 + g;
            const uint32_t* ph = reinterpret_cast<const uint32_t*>(xhi) + n * SROW2;
            const uint32_t* pl = reinterpret_cast<const uint32_t*>(xlo) + n * SROW2;
            bh0[nfi] = ph[ki]; bh1[nfi] = ph[ki + 4];
            bl0[nfi] = pl[ki]; bl1[nfi] = pl[ki + 4];
        }

        // product-major MMA stream: same-acc dependency distance = 4
        #pragma unroll
        for (int nfi = 0; nfi < 4; ++nfi)
            mma_bf16(d[nfi], ah0, ah1, ah2, ah0, bh0[nfi], bh1[nfi]);
        #pragma unroll
        for (int nfi = 0; nfi < 4; ++nfi)
            mma_bf16(d[nfi], ah0, ah1, ah2, ah0, bl0[nfi], bl1[nfi]);
        #pragma unroll
        for (int nfi = 0; nfi < 4; ++nfi)
            mma_bf16(d[nfi], al0, al1, al2, al0, bh0[nfi], bh1[nfi]);
    }

    // -- epilogue: D[m,n] -> out[rb + n, col0 + m] ------------------------------
    #pragma unroll
    for (int nfi = 0; nfi < 4; ++nfi) {
        const size_t n0 = (size_t)(rb + nfi * 8 + 2 * t) * L_LEN;
        out[n0 + mg]             = d[nfi][0];
        out[n0 + L_LEN + mg]     = d[nfi][1];
        out[n0 + mg + 8]         = d[nfi][2];
        out[n0 + L_LEN + mg + 8] = d[nfi][3];
    }
}

extern "C" void kernel_launch(void* const* d_in, const int* in_sizes, int n_in,
                              void* d_out, int out_size) {
    const float* x  = (const float*)d_in[0];   // [64, 65536] fp32
    const float* tw = (const float*)d_in[1];   // [4] fp32
    float* out = (float*)d_out;

    cudaFuncSetAttribute(hann_mma_kernel,
                         cudaFuncAttributeMaxDynamicSharedMemorySize, SM_TOTAL);
    dim3 grid(L_LEN / TILE_M, 64 / ROWS);      // (512, 2) = 1024 CTAs
    hann_mma_kernel<<<grid, THREADS, SM_TOTAL>>>(x, tw, out);
}